// round 1
// baseline (speedup 1.0000x reference)
#include <cuda_runtime.h>
#include <math.h>

#define B_   2
#define T_   2048
#define D_   1024
#define H_   8
#define DK   64
#define DV   64
#define R_   64
#define DFF  4096
#define BT   (B_*T_)       // 4096
#define HD   (H_*DK)       // 512

// ---------------- scratch (device globals; no allocation allowed) ----------------
__device__ float g_tmp  [BT*D_];    // rms-normed input
__device__ float g_h    [BT*D_];    // conv+silu output
__device__ float g_q    [BT*HD];
__device__ float g_k    [BT*HD];
__device__ float g_v    [BT*HD];
__device__ float g_drive[BT*HD];
__device__ float g_ab   [BT*HD];
__device__ float g_au   [BT*R_];
__device__ float g_beta [BT*H_];
__device__ float g_yattn[BT*HD];
__device__ float g_u1   [BT*R_];
__device__ float g_gate [BT*D_];
__device__ float g_y2   [BT*D_];
__device__ float g_z    [BT*D_];
__device__ float g_ffa  [BT*DFF];

// ---------------- elementwise / norm kernels ----------------

__global__ void rmsnorm_kernel(const float* __restrict__ x, const float* __restrict__ w,
                               float* __restrict__ out) {
    int row = blockIdx.x;
    const float* xr = x + (size_t)row * D_;
    float ss = 0.f;
    for (int i = threadIdx.x; i < D_; i += 256) { float v = xr[i]; ss += v * v; }
    #pragma unroll
    for (int o = 16; o; o >>= 1) ss += __shfl_down_sync(0xffffffffu, ss, o);
    __shared__ float sh[8];
    int lane = threadIdx.x & 31, warp = threadIdx.x >> 5;
    if (lane == 0) sh[warp] = ss;
    __syncthreads();
    if (warp == 0) {
        ss = (lane < 8) ? sh[lane] : 0.f;
        #pragma unroll
        for (int o = 4; o; o >>= 1) ss += __shfl_down_sync(0xffffffffu, ss, o);
        if (lane == 0) sh[0] = ss;
    }
    __syncthreads();
    float inv = rsqrtf(sh[0] * (1.f / D_) + 1e-6f);
    for (int i = threadIdx.x; i < D_; i += 256)
        out[(size_t)row * D_ + i] = xr[i] * inv * w[i];
}

// causal depthwise conv (KW=4) + bias + SiLU
__global__ void conv_silu_kernel(const float* __restrict__ hin, const float* __restrict__ w,
                                 const float* __restrict__ b, float* __restrict__ out) {
    int idx = blockIdx.x * blockDim.x + threadIdx.x;
    if (idx >= BT * D_) return;
    int d = idx % D_;
    int bt = idx / D_;
    int t = bt % T_;
    float acc = b[d];
    #pragma unroll
    for (int j = 0; j < 4; j++) {
        int tt = t - 3 + j;
        if (tt >= 0) acc += hin[(size_t)(bt - 3 + j) * D_ + d] * w[d * 4 + j];
    }
    out[idx] = acc / (1.f + __expf(-acc));  // silu
}

// per (row,head) L2 normalize: v / (||v|| + 1e-6), 64 threads/block
__global__ void l2norm_kernel(float* __restrict__ p) {
    size_t base = (size_t)blockIdx.x * 64;
    float v = p[base + threadIdx.x];
    float ss = v * v;
    #pragma unroll
    for (int o = 16; o; o >>= 1) ss += __shfl_down_sync(0xffffffffu, ss, o);
    __shared__ float sh[2];
    if ((threadIdx.x & 31) == 0) sh[threadIdx.x >> 5] = ss;
    __syncthreads();
    float tot = sh[0] + sh[1];
    p[base + threadIdx.x] = v / (sqrtf(tot) + 1e-6f);
}

// per (row,head) RMS norm * head weight
__global__ void headnorm_kernel(float* __restrict__ p, const float* __restrict__ w) {
    int h = blockIdx.x % H_;
    size_t base = (size_t)blockIdx.x * 64;
    float v = p[base + threadIdx.x];
    float ss = v * v;
    #pragma unroll
    for (int o = 16; o; o >>= 1) ss += __shfl_down_sync(0xffffffffu, ss, o);
    __shared__ float sh[2];
    if ((threadIdx.x & 31) == 0) sh[threadIdx.x >> 5] = ss;
    __syncthreads();
    float mean = (sh[0] + sh[1]) * (1.f / 64.f);
    p[base + threadIdx.x] = v * rsqrtf(mean + 1e-6f) * w[h * 64 + threadIdx.x];
}

// ---------------- tiled SGEMM with fused epilogues ----------------
// C[M,N] = A[M,K] @ B[K,N], M%64==0, K%16==0 (K%4==0 for float4 A-loads)

enum { EP_NONE = 0, EP_BIAS = 1, EP_BIAS_SILU = 2, EP_BIAS_SIGMOID = 3,
       EP_RESID_GATE = 4, EP_RESID_ADD = 5 };

__global__ void __launch_bounds__(256)
sgemm_kernel(const float* __restrict__ A, const float* __restrict__ Bm,
             const float* __restrict__ bias, const float* __restrict__ resid,
             const float* __restrict__ gate, float* __restrict__ C,
             int M, int N, int K, int mode) {
    __shared__ float As[16][68];
    __shared__ float Bs[16][64];
    int tid = threadIdx.x;
    int tx = tid & 15, ty = tid >> 4;
    int row0 = blockIdx.y * 64;
    int col0 = blockIdx.x * 64;

    int aRow = tid >> 2, aCol = (tid & 3) * 4;
    int bRow = tid >> 4, bCol = (tid & 15) * 4;
    const bool fullN = (col0 + 64 <= N);

    float acc[4][4];
    #pragma unroll
    for (int i = 0; i < 4; i++)
        #pragma unroll
        for (int j = 0; j < 4; j++) acc[i][j] = 0.f;

    for (int k0 = 0; k0 < K; k0 += 16) {
        float4 av = *reinterpret_cast<const float4*>(&A[(size_t)(row0 + aRow) * K + k0 + aCol]);
        As[aCol + 0][aRow] = av.x; As[aCol + 1][aRow] = av.y;
        As[aCol + 2][aRow] = av.z; As[aCol + 3][aRow] = av.w;
        if (fullN) {
            *reinterpret_cast<float4*>(&Bs[bRow][bCol]) =
                *reinterpret_cast<const float4*>(&Bm[(size_t)(k0 + bRow) * N + col0 + bCol]);
        } else {
            #pragma unroll
            for (int u = 0; u < 4; u++) {
                int c = col0 + bCol + u;
                Bs[bRow][bCol + u] = (c < N) ? Bm[(size_t)(k0 + bRow) * N + c] : 0.f;
            }
        }
        __syncthreads();
        #pragma unroll
        for (int kk = 0; kk < 16; kk++) {
            float a[4], b[4];
            *reinterpret_cast<float4*>(a) = *reinterpret_cast<const float4*>(&As[kk][ty * 4]);
            *reinterpret_cast<float4*>(b) = *reinterpret_cast<const float4*>(&Bs[kk][tx * 4]);
            #pragma unroll
            for (int i = 0; i < 4; i++)
                #pragma unroll
                for (int j = 0; j < 4; j++) acc[i][j] = fmaf(a[i], b[j], acc[i][j]);
        }
        __syncthreads();
    }

    #pragma unroll
    for (int i = 0; i < 4; i++) {
        int r = row0 + ty * 4 + i;
        #pragma unroll
        for (int j = 0; j < 4; j++) {
            int c = col0 + tx * 4 + j;
            if (c >= N) continue;
            float a = acc[i][j], o;
            if (mode == EP_NONE) o = a;
            else if (mode == EP_BIAS) o = a + bias[c];
            else if (mode == EP_BIAS_SILU) { float t = a + bias[c]; o = t / (1.f + __expf(-t)); }
            else if (mode == EP_BIAS_SIGMOID) { float t = a + bias[c]; o = 1.f / (1.f + __expf(-t)); }
            else if (mode == EP_RESID_GATE) o = resid[(size_t)r * N + c] + a * gate[(size_t)r * N + c];
            else o = resid[(size_t)r * N + c] + a;  // EP_RESID_ADD
            C[(size_t)r * N + c] = o;
        }
    }
}

// dual GEMM: C = silu(A@B1) * (A@B3), N%64==0
__global__ void __launch_bounds__(256)
sgemm_dual_kernel(const float* __restrict__ A, const float* __restrict__ B1,
                  const float* __restrict__ B3, float* __restrict__ C,
                  int M, int N, int K) {
    __shared__ float As[16][68];
    __shared__ float Bs1[16][64];
    __shared__ float Bs3[16][64];
    int tid = threadIdx.x;
    int tx = tid & 15, ty = tid >> 4;
    int row0 = blockIdx.y * 64;
    int col0 = blockIdx.x * 64;
    int aRow = tid >> 2, aCol = (tid & 3) * 4;
    int bRow = tid >> 4, bCol = (tid & 15) * 4;

    float acc1[4][4], acc3[4][4];
    #pragma unroll
    for (int i = 0; i < 4; i++)
        #pragma unroll
        for (int j = 0; j < 4; j++) { acc1[i][j] = 0.f; acc3[i][j] = 0.f; }

    for (int k0 = 0; k0 < K; k0 += 16) {
        float4 av = *reinterpret_cast<const float4*>(&A[(size_t)(row0 + aRow) * K + k0 + aCol]);
        As[aCol + 0][aRow] = av.x; As[aCol + 1][aRow] = av.y;
        As[aCol + 2][aRow] = av.z; As[aCol + 3][aRow] = av.w;
        *reinterpret_cast<float4*>(&Bs1[bRow][bCol]) =
            *reinterpret_cast<const float4*>(&B1[(size_t)(k0 + bRow) * N + col0 + bCol]);
        *reinterpret_cast<float4*>(&Bs3[bRow][bCol]) =
            *reinterpret_cast<const float4*>(&B3[(size_t)(k0 + bRow) * N + col0 + bCol]);
        __syncthreads();
        #pragma unroll
        for (int kk = 0; kk < 16; kk++) {
            float a[4], b1[4], b3[4];
            *reinterpret_cast<float4*>(a)  = *reinterpret_cast<const float4*>(&As[kk][ty * 4]);
            *reinterpret_cast<float4*>(b1) = *reinterpret_cast<const float4*>(&Bs1[kk][tx * 4]);
            *reinterpret_cast<float4*>(b3) = *reinterpret_cast<const float4*>(&Bs3[kk][tx * 4]);
            #pragma unroll
            for (int i = 0; i < 4; i++)
                #pragma unroll
                for (int j = 0; j < 4; j++) {
                    acc1[i][j] = fmaf(a[i], b1[j], acc1[i][j]);
                    acc3[i][j] = fmaf(a[i], b3[j], acc3[i][j]);
                }
        }
        __syncthreads();
    }
    #pragma unroll
    for (int i = 0; i < 4; i++) {
        int r = row0 + ty * 4 + i;
        #pragma unroll
        for (int j = 0; j < 4; j++) {
            int c = col0 + tx * 4 + j;
            float t = acc1[i][j];
            C[(size_t)r * N + c] = (t / (1.f + __expf(-t))) * acc3[i][j];
        }
    }
}

// ---------------- sequential LIF + gated delta-rule scan ----------------
// one block per (b,h); 256 threads: j = tid&63 (dv column), g = tid>>6 (dk group)
__global__ void __launch_bounds__(256)
scan_kernel(const float* __restrict__ q, const float* __restrict__ k,
            const float* __restrict__ v, const float* __restrict__ drive,
            const float* __restrict__ ab, const float* __restrict__ betab,
            const float* __restrict__ asp, const float* __restrict__ bsp,
            float* __restrict__ yout) {
    int bh = blockIdx.x;
    int b = bh / H_, h = bh % H_;
    int tid = threadIdx.x;
    int j = tid & 63, g = tid >> 6;

    __shared__ float sk[64], sq[64], sv[64], salpha[64], sspb[64];
    __shared__ float sred1[4][64], sred2[4][64];
    __shared__ float sbeta;

    float s[16];
    #pragma unroll
    for (int ii = 0; ii < 16; ii++) s[ii] = 0.f;

    float m = 0.f, aspv = 0.f, bspv = 0.f;
    if (tid < 64) { aspv = asp[h * 64 + tid]; bspv = bsp[h * 64 + tid]; }

    size_t rowbase = (size_t)(b * T_) * HD + (size_t)h * 64;
    const float* bb = betab + (size_t)(b * T_) * H_ + h;

    for (int t = 0; t < T_; t++) {
        size_t qo = rowbase + (size_t)t * HD;
        float myspike = 0.f;
        if (tid < 64) {
            int i = tid;
            m = 0.9f * m + drive[qo + i];
            float spk = (m > 0.5f) ? 1.f : 0.f;
            m -= spk * 0.5f;
            myspike = spk;
            float araw = ab[qo + i] + aspv * spk;
            salpha[i] = 1.f / (1.f + __expf(-araw));
            sspb[i] = spk * bspv;
            sk[i] = k[qo + i];
            sq[i] = q[qo + i];
        } else if (tid < 128) {
            sv[tid - 64] = v[qo + (tid - 64)];
        }
        int nspk = __syncthreads_count((tid < 64) && (myspike > 0.5f));
        bool active = nspk > 0;
        if (tid < 32) {
            float sbv = sspb[tid] + sspb[tid + 32];
            #pragma unroll
            for (int o = 16; o; o >>= 1) sbv += __shfl_down_sync(0xffffffffu, sbv, o);
            if (tid == 0) sbeta = sbv;
        }
        float predp = 0.f;
        #pragma unroll
        for (int ii = 0; ii < 16; ii++) {
            int i = (g << 4) + ii;
            float a = active ? salpha[i] : 1.f;
            float sval = s[ii] * a;
            s[ii] = sval;
            predp = fmaf(sk[i], sval, predp);
        }
        sred1[g][j] = predp;
        __syncthreads();
        float pred = sred1[0][j] + sred1[1][j] + sred1[2][j] + sred1[3][j];
        float beta = 0.f;
        if (active) {
            float braw = bb[(size_t)t * H_] + sbeta;
            beta = 1.f / (1.f + __expf(-braw));
        }
        float bd = beta * (sv[j] - pred);
        float outp = 0.f;
        #pragma unroll
        for (int ii = 0; ii < 16; ii++) {
            int i = (g << 4) + ii;
            float sval = fmaf(sk[i], bd, s[ii]);
            s[ii] = sval;
            outp = fmaf(sq[i], sval, outp);
        }
        sred2[g][j] = outp;
        __syncthreads();
        if (g == 0) yout[qo + j] = sred2[0][j] + sred2[1][j] + sred2[2][j] + sred2[3][j];
    }
}

// ---------------- host launch ----------------

template <typename Tsym>
static float* symaddr(const Tsym& s) {
    void* p = nullptr;
    cudaGetSymbolAddress(&p, s);
    return (float*)p;
}

static void gemm(const float* A, const float* Bm, const float* bias,
                 const float* resid, const float* gate, float* C,
                 int M, int N, int K, int mode) {
    dim3 grid((N + 63) / 64, M / 64);
    sgemm_kernel<<<grid, 256>>>(A, Bm, bias, resid, gate, C, M, N, K, mode);
}

extern "C" void kernel_launch(void* const* d_in, const int* in_sizes, int n_in,
                              void* d_out, int out_size) {
    const float* x          = (const float*)d_in[0];
    const float* norm_in_w  = (const float*)d_in[1];
    const float* conv_w     = (const float*)d_in[2];
    const float* conv_b     = (const float*)d_in[3];
    const float* Wq         = (const float*)d_in[4];
    const float* Wk         = (const float*)d_in[5];
    const float* Wv         = (const float*)d_in[6];
    const float* Wo         = (const float*)d_in[7];
    const float* Wspike     = (const float*)d_in[8];
    const float* Wau        = (const float*)d_in[9];
    const float* bau        = (const float*)d_in[10];
    const float* Wad        = (const float*)d_in[11];
    const float* bad        = (const float*)d_in[12];
    const float* alpha_sp   = (const float*)d_in[13];
    const float* Wbeta      = (const float*)d_in[14];
    const float* bbeta      = (const float*)d_in[15];
    const float* beta_sp    = (const float*)d_in[16];
    const float* head_nw    = (const float*)d_in[17];
    const float* Wu1        = (const float*)d_in[18];
    const float* bu1        = (const float*)d_in[19];
    const float* Wu2        = (const float*)d_in[20];
    const float* bu2        = (const float*)d_in[21];
    const float* ff_norm_w  = (const float*)d_in[22];
    const float* Wff1       = (const float*)d_in[23];
    const float* Wff3       = (const float*)d_in[24];
    const float* Wff2       = (const float*)d_in[25];
    float* out = (float*)d_out;

    float* p_tmp   = symaddr(g_tmp);
    float* p_h     = symaddr(g_h);
    float* p_q     = symaddr(g_q);
    float* p_k     = symaddr(g_k);
    float* p_v     = symaddr(g_v);
    float* p_drive = symaddr(g_drive);
    float* p_ab    = symaddr(g_ab);
    float* p_au    = symaddr(g_au);
    float* p_beta  = symaddr(g_beta);
    float* p_yattn = symaddr(g_yattn);
    float* p_u1    = symaddr(g_u1);
    float* p_gate  = symaddr(g_gate);
    float* p_y2    = symaddr(g_y2);
    float* p_z     = symaddr(g_z);
    float* p_ffa   = symaddr(g_ffa);

    // 1) input RMS norm
    rmsnorm_kernel<<<BT, 256>>>(x, norm_in_w, p_tmp);
    // 2) causal depthwise conv + silu
    conv_silu_kernel<<<(BT * D_ + 255) / 256, 256>>>(p_tmp, conv_w, conv_b, p_h);
    // 3) projections
    gemm(p_h, Wq,     nullptr, nullptr, nullptr, p_q,     BT, HD, D_, EP_NONE);
    gemm(p_h, Wk,     nullptr, nullptr, nullptr, p_k,     BT, HD, D_, EP_NONE);
    gemm(p_h, Wv,     nullptr, nullptr, nullptr, p_v,     BT, HD, D_, EP_NONE);
    gemm(p_h, Wspike, nullptr, nullptr, nullptr, p_drive, BT, HD, D_, EP_NONE);
    // 4) alpha path: silu(h@Wau+bau)@Wad+bad
    gemm(p_h, Wau, bau, nullptr, nullptr, p_au, BT, R_, D_, EP_BIAS_SILU);
    gemm(p_au, Wad, bad, nullptr, nullptr, p_ab, BT, HD, R_, EP_BIAS);
    // 5) beta base
    gemm(p_h, Wbeta, bbeta, nullptr, nullptr, p_beta, BT, H_, D_, EP_BIAS);
    // 6) q/k L2 normalize per head
    l2norm_kernel<<<BT * H_, 64>>>(p_q);
    l2norm_kernel<<<BT * H_, 64>>>(p_k);
    // 7) output gate: sigmoid(silu(x@Wu1+bu1)@Wu2+bu2)
    gemm(x, Wu1, bu1, nullptr, nullptr, p_u1, BT, R_, D_, EP_BIAS_SILU);
    gemm(p_u1, Wu2, bu2, nullptr, nullptr, p_gate, BT, D_, R_, EP_BIAS_SIGMOID);
    // 8) sequential LIF + delta-rule scan
    scan_kernel<<<B_ * H_, 256>>>(p_q, p_k, p_v, p_drive, p_ab, p_beta,
                                  alpha_sp, beta_sp, p_yattn);
    // 9) headwise RMS norm
    headnorm_kernel<<<BT * H_, 64>>>(p_yattn, head_nw);
    // 10) y2 = x + (yattn@Wo) * gate
    gemm(p_yattn, Wo, nullptr, x, p_gate, p_y2, BT, D_, HD, EP_RESID_GATE);
    // 11) FFN: z = rms(y2); ffa = silu(z@Wff1)*(z@Wff3); out = y2 + ffa@Wff2
    rmsnorm_kernel<<<BT, 256>>>(p_y2, ff_norm_w, p_z);
    {
        dim3 grid(DFF / 64, BT / 64);
        sgemm_dual_kernel<<<grid, 256>>>(p_z, Wff1, Wff3, p_ffa, BT, DFF, D_);
    }
    gemm(p_ffa, Wff2, nullptr, p_y2, nullptr, out, BT, D_, DFF, EP_RESID_ADD);
}

// round 2
// speedup vs baseline: 1.0983x; 1.0983x over previous
#include <cuda_runtime.h>
#include <mma.h>
#include <math.h>

using namespace nvcuda;

#define B_   2
#define T_   2048
#define D_   1024
#define H_   8
#define DK   64
#define DV   64
#define R_   64
#define DFF  4096
#define BT   (B_*T_)       // 4096
#define HD   (H_*DK)       // 512

// ---------------- scratch (device globals; no allocation allowed) ----------------
__device__ float g_tmp  [BT*D_];
__device__ float g_h    [BT*D_];
__device__ float g_q    [BT*HD];
__device__ float g_k    [BT*HD];
__device__ float g_v    [BT*HD];
__device__ float g_drive[BT*HD];
__device__ float g_ab   [BT*HD];
__device__ float g_au   [BT*R_];
__device__ float g_beta [BT*H_];
__device__ float g_yattn[BT*HD];
__device__ float g_u1   [BT*R_];
__device__ float g_gate [BT*D_];
__device__ float g_y2   [BT*D_];
__device__ float g_z    [BT*D_];
__device__ float g_ffa  [BT*DFF];

// ---------------- elementwise / norm kernels ----------------

__global__ void rmsnorm_kernel(const float* __restrict__ x, const float* __restrict__ w,
                               float* __restrict__ out) {
    int row = blockIdx.x;
    const float* xr = x + (size_t)row * D_;
    float ss = 0.f;
    for (int i = threadIdx.x; i < D_; i += 256) { float v = xr[i]; ss += v * v; }
    #pragma unroll
    for (int o = 16; o; o >>= 1) ss += __shfl_down_sync(0xffffffffu, ss, o);
    __shared__ float sh[8];
    int lane = threadIdx.x & 31, warp = threadIdx.x >> 5;
    if (lane == 0) sh[warp] = ss;
    __syncthreads();
    if (warp == 0) {
        ss = (lane < 8) ? sh[lane] : 0.f;
        #pragma unroll
        for (int o = 4; o; o >>= 1) ss += __shfl_down_sync(0xffffffffu, ss, o);
        if (lane == 0) sh[0] = ss;
    }
    __syncthreads();
    float inv = rsqrtf(sh[0] * (1.f / D_) + 1e-6f);
    for (int i = threadIdx.x; i < D_; i += 256)
        out[(size_t)row * D_ + i] = xr[i] * inv * w[i];
}

__global__ void conv_silu_kernel(const float* __restrict__ hin, const float* __restrict__ w,
                                 const float* __restrict__ b, float* __restrict__ out) {
    int idx = blockIdx.x * blockDim.x + threadIdx.x;
    if (idx >= BT * D_) return;
    int d = idx % D_;
    int bt = idx / D_;
    int t = bt % T_;
    float acc = b[d];
    #pragma unroll
    for (int j = 0; j < 4; j++) {
        int tt = t - 3 + j;
        if (tt >= 0) acc += hin[(size_t)(bt - 3 + j) * D_ + d] * w[d * 4 + j];
    }
    out[idx] = acc / (1.f + __expf(-acc));
}

__global__ void l2norm_kernel(float* __restrict__ p) {
    size_t base = (size_t)blockIdx.x * 64;
    float v = p[base + threadIdx.x];
    float ss = v * v;
    #pragma unroll
    for (int o = 16; o; o >>= 1) ss += __shfl_down_sync(0xffffffffu, ss, o);
    __shared__ float sh[2];
    if ((threadIdx.x & 31) == 0) sh[threadIdx.x >> 5] = ss;
    __syncthreads();
    float tot = sh[0] + sh[1];
    p[base + threadIdx.x] = v / (sqrtf(tot) + 1e-6f);
}

__global__ void headnorm_kernel(float* __restrict__ p, const float* __restrict__ w) {
    int h = blockIdx.x % H_;
    size_t base = (size_t)blockIdx.x * 64;
    float v = p[base + threadIdx.x];
    float ss = v * v;
    #pragma unroll
    for (int o = 16; o; o >>= 1) ss += __shfl_down_sync(0xffffffffu, ss, o);
    __shared__ float sh[2];
    if ((threadIdx.x & 31) == 0) sh[threadIdx.x >> 5] = ss;
    __syncthreads();
    float mean = (sh[0] + sh[1]) * (1.f / 64.f);
    p[base + threadIdx.x] = v * rsqrtf(mean + 1e-6f) * w[h * 64 + threadIdx.x];
}

// ---------------- fp32 SIMT GEMM (kept for spike path + small GEMMs) ----------------

enum { EP_NONE = 0, EP_BIAS = 1, EP_BIAS_SILU = 2, EP_BIAS_SIGMOID = 3,
       EP_RESID_GATE = 4, EP_RESID_ADD = 5 };

__global__ void __launch_bounds__(256)
sgemm_kernel(const float* __restrict__ A, const float* __restrict__ Bm,
             const float* __restrict__ bias, const float* __restrict__ resid,
             const float* __restrict__ gate, float* __restrict__ C,
             int M, int N, int K, int mode) {
    __shared__ float As[16][68];
    __shared__ float Bs[16][64];
    int tid = threadIdx.x;
    int tx = tid & 15, ty = tid >> 4;
    int row0 = blockIdx.y * 64;
    int col0 = blockIdx.x * 64;

    int aRow = tid >> 2, aCol = (tid & 3) * 4;
    int bRow = tid >> 4, bCol = (tid & 15) * 4;
    const bool fullN = (col0 + 64 <= N);

    float acc[4][4];
    #pragma unroll
    for (int i = 0; i < 4; i++)
        #pragma unroll
        for (int j = 0; j < 4; j++) acc[i][j] = 0.f;

    for (int k0 = 0; k0 < K; k0 += 16) {
        float4 av = *reinterpret_cast<const float4*>(&A[(size_t)(row0 + aRow) * K + k0 + aCol]);
        As[aCol + 0][aRow] = av.x; As[aCol + 1][aRow] = av.y;
        As[aCol + 2][aRow] = av.z; As[aCol + 3][aRow] = av.w;
        if (fullN) {
            *reinterpret_cast<float4*>(&Bs[bRow][bCol]) =
                *reinterpret_cast<const float4*>(&Bm[(size_t)(k0 + bRow) * N + col0 + bCol]);
        } else {
            #pragma unroll
            for (int u = 0; u < 4; u++) {
                int c = col0 + bCol + u;
                Bs[bRow][bCol + u] = (c < N) ? Bm[(size_t)(k0 + bRow) * N + c] : 0.f;
            }
        }
        __syncthreads();
        #pragma unroll
        for (int kk = 0; kk < 16; kk++) {
            float a[4], b[4];
            *reinterpret_cast<float4*>(a) = *reinterpret_cast<const float4*>(&As[kk][ty * 4]);
            *reinterpret_cast<float4*>(b) = *reinterpret_cast<const float4*>(&Bs[kk][tx * 4]);
            #pragma unroll
            for (int i = 0; i < 4; i++)
                #pragma unroll
                for (int j = 0; j < 4; j++) acc[i][j] = fmaf(a[i], b[j], acc[i][j]);
        }
        __syncthreads();
    }

    #pragma unroll
    for (int i = 0; i < 4; i++) {
        int r = row0 + ty * 4 + i;
        #pragma unroll
        for (int j = 0; j < 4; j++) {
            int c = col0 + tx * 4 + j;
            if (c >= N) continue;
            float a = acc[i][j], o;
            if (mode == EP_NONE) o = a;
            else if (mode == EP_BIAS) o = a + bias[c];
            else if (mode == EP_BIAS_SILU) { float t = a + bias[c]; o = t / (1.f + __expf(-t)); }
            else if (mode == EP_BIAS_SIGMOID) { float t = a + bias[c]; o = 1.f / (1.f + __expf(-t)); }
            else if (mode == EP_RESID_GATE) o = resid[(size_t)r * N + c] + a * gate[(size_t)r * N + c];
            else o = resid[(size_t)r * N + c] + a;
            C[(size_t)r * N + c] = o;
        }
    }
}

// ---------------- tf32 tensor-core GEMM (wmma, fp32 accumulate) ----------------
// C[M,N] = A[M,K] @ B[K,N]; M%128==0, N%128==0, K%32==0.
// Block 256 thr (8 warps, 4x2), block tile 128x128, warp tile 32x64.

__global__ void __launch_bounds__(256)
tf32_gemm_kernel(const float* __restrict__ A, const float* __restrict__ Bm,
                 const float* __restrict__ resid, const float* __restrict__ gate,
                 float* __restrict__ C, int M, int N, int K, int mode) {
    __shared__ float sA[128 * 32];
    __shared__ float sB[32 * 128];
    int tid = threadIdx.x;
    int warp = tid >> 5;
    int warpM = warp & 3;        // 0..3
    int warpN = warp >> 2;       // 0..1
    int row0 = blockIdx.y * 128;
    int col0 = blockIdx.x * 128;

    wmma::fragment<wmma::accumulator, 16, 16, 8, float> acc[2][4];
    #pragma unroll
    for (int i = 0; i < 2; i++)
        #pragma unroll
        for (int j = 0; j < 4; j++) wmma::fill_fragment(acc[i][j], 0.f);

    for (int k0 = 0; k0 < K; k0 += 32) {
        // load A tile 128x32 (4 float4 / thread)
        #pragma unroll
        for (int i = 0; i < 4; i++) {
            int lin = tid + 256 * i;          // float4 index
            int r = lin >> 3, c = (lin & 7) << 2;
            *reinterpret_cast<float4*>(&sA[r * 32 + c]) =
                *reinterpret_cast<const float4*>(&A[(size_t)(row0 + r) * K + k0 + c]);
        }
        // load B tile 32x128
        #pragma unroll
        for (int i = 0; i < 4; i++) {
            int lin = tid + 256 * i;
            int r = lin >> 5, c = (lin & 31) << 2;
            *reinterpret_cast<float4*>(&sB[r * 128 + c]) =
                *reinterpret_cast<const float4*>(&Bm[(size_t)(k0 + r) * N + col0 + c]);
        }
        __syncthreads();
        #pragma unroll
        for (int kk = 0; kk < 32; kk += 8) {
            wmma::fragment<wmma::matrix_a, 16, 16, 8, wmma::precision::tf32, wmma::row_major> af[2];
            wmma::fragment<wmma::matrix_b, 16, 16, 8, wmma::precision::tf32, wmma::row_major> bf[4];
            #pragma unroll
            for (int i = 0; i < 2; i++) {
                wmma::load_matrix_sync(af[i], &sA[(warpM * 32 + i * 16) * 32 + kk], 32);
                #pragma unroll
                for (int e = 0; e < af[i].num_elements; e++)
                    af[i].x[e] = wmma::__float_to_tf32(af[i].x[e]);
            }
            #pragma unroll
            for (int j = 0; j < 4; j++) {
                wmma::load_matrix_sync(bf[j], &sB[kk * 128 + warpN * 64 + j * 16], 128);
                #pragma unroll
                for (int e = 0; e < bf[j].num_elements; e++)
                    bf[j].x[e] = wmma::__float_to_tf32(bf[j].x[e]);
            }
            #pragma unroll
            for (int i = 0; i < 2; i++)
                #pragma unroll
                for (int j = 0; j < 4; j++)
                    wmma::mma_sync(acc[i][j], af[i], bf[j], acc[i][j]);
        }
        __syncthreads();
    }

    #pragma unroll
    for (int i = 0; i < 2; i++) {
        #pragma unroll
        for (int j = 0; j < 4; j++) {
            int r = row0 + warpM * 32 + i * 16;
            int c = col0 + warpN * 64 + j * 16;
            float* cp = &C[(size_t)r * N + c];
            if (mode == EP_RESID_ADD) {
                wmma::fragment<wmma::accumulator, 16, 16, 8, float> rf;
                wmma::load_matrix_sync(rf, &resid[(size_t)r * N + c], N, wmma::mem_row_major);
                #pragma unroll
                for (int e = 0; e < rf.num_elements; e++) acc[i][j].x[e] += rf.x[e];
            } else if (mode == EP_RESID_GATE) {
                wmma::fragment<wmma::accumulator, 16, 16, 8, float> rf, gf;
                wmma::load_matrix_sync(rf, &resid[(size_t)r * N + c], N, wmma::mem_row_major);
                wmma::load_matrix_sync(gf, &gate[(size_t)r * N + c], N, wmma::mem_row_major);
                #pragma unroll
                for (int e = 0; e < rf.num_elements; e++)
                    acc[i][j].x[e] = rf.x[e] + acc[i][j].x[e] * gf.x[e];
            }
            wmma::store_matrix_sync(cp, acc[i][j], N, wmma::mem_row_major);
        }
    }
}

// tf32 dual GEMM: C = silu(A@B1) * (A@B3). Block tile 128x64, warp tile 32x32.
__global__ void __launch_bounds__(256)
tf32_dual_kernel(const float* __restrict__ A, const float* __restrict__ B1,
                 const float* __restrict__ B3, float* __restrict__ C,
                 int M, int N, int K) {
    __shared__ float sA[128 * 32];
    __shared__ float sB1[32 * 64];
    __shared__ float sB3[32 * 64];
    int tid = threadIdx.x;
    int warp = tid >> 5;
    int warpM = warp & 3;
    int warpN = warp >> 2;
    int row0 = blockIdx.y * 128;
    int col0 = blockIdx.x * 64;

    wmma::fragment<wmma::accumulator, 16, 16, 8, float> acc1[2][2], acc3[2][2];
    #pragma unroll
    for (int i = 0; i < 2; i++)
        #pragma unroll
        for (int j = 0; j < 2; j++) { wmma::fill_fragment(acc1[i][j], 0.f); wmma::fill_fragment(acc3[i][j], 0.f); }

    for (int k0 = 0; k0 < K; k0 += 32) {
        #pragma unroll
        for (int i = 0; i < 4; i++) {
            int lin = tid + 256 * i;
            int r = lin >> 3, c = (lin & 7) << 2;
            *reinterpret_cast<float4*>(&sA[r * 32 + c]) =
                *reinterpret_cast<const float4*>(&A[(size_t)(row0 + r) * K + k0 + c]);
        }
        #pragma unroll
        for (int i = 0; i < 2; i++) {
            int lin = tid + 256 * i;
            int r = lin >> 4, c = (lin & 15) << 2;
            *reinterpret_cast<float4*>(&sB1[r * 64 + c]) =
                *reinterpret_cast<const float4*>(&B1[(size_t)(k0 + r) * N + col0 + c]);
            *reinterpret_cast<float4*>(&sB3[r * 64 + c]) =
                *reinterpret_cast<const float4*>(&B3[(size_t)(k0 + r) * N + col0 + c]);
        }
        __syncthreads();
        #pragma unroll
        for (int kk = 0; kk < 32; kk += 8) {
            wmma::fragment<wmma::matrix_a, 16, 16, 8, wmma::precision::tf32, wmma::row_major> af[2];
            wmma::fragment<wmma::matrix_b, 16, 16, 8, wmma::precision::tf32, wmma::row_major> b1f[2], b3f[2];
            #pragma unroll
            for (int i = 0; i < 2; i++) {
                wmma::load_matrix_sync(af[i], &sA[(warpM * 32 + i * 16) * 32 + kk], 32);
                #pragma unroll
                for (int e = 0; e < af[i].num_elements; e++)
                    af[i].x[e] = wmma::__float_to_tf32(af[i].x[e]);
            }
            #pragma unroll
            for (int j = 0; j < 2; j++) {
                wmma::load_matrix_sync(b1f[j], &sB1[kk * 64 + warpN * 32 + j * 16], 64);
                wmma::load_matrix_sync(b3f[j], &sB3[kk * 64 + warpN * 32 + j * 16], 64);
                #pragma unroll
                for (int e = 0; e < b1f[j].num_elements; e++) {
                    b1f[j].x[e] = wmma::__float_to_tf32(b1f[j].x[e]);
                    b3f[j].x[e] = wmma::__float_to_tf32(b3f[j].x[e]);
                }
            }
            #pragma unroll
            for (int i = 0; i < 2; i++)
                #pragma unroll
                for (int j = 0; j < 2; j++) {
                    wmma::mma_sync(acc1[i][j], af[i], b1f[j], acc1[i][j]);
                    wmma::mma_sync(acc3[i][j], af[i], b3f[j], acc3[i][j]);
                }
        }
        __syncthreads();
    }

    #pragma unroll
    for (int i = 0; i < 2; i++)
        #pragma unroll
        for (int j = 0; j < 2; j++) {
            #pragma unroll
            for (int e = 0; e < acc1[i][j].num_elements; e++) {
                float t = acc1[i][j].x[e];
                acc1[i][j].x[e] = (t / (1.f + __expf(-t))) * acc3[i][j].x[e];
            }
            int r = row0 + warpM * 32 + i * 16;
            int c = col0 + warpN * 32 + j * 16;
            wmma::store_matrix_sync(&C[(size_t)r * N + c], acc1[i][j], N, wmma::mem_row_major);
        }
}

// ---------------- sequential LIF + gated delta-rule scan ----------------
__global__ void __launch_bounds__(256)
scan_kernel(const float* __restrict__ q, const float* __restrict__ k,
            const float* __restrict__ v, const float* __restrict__ drive,
            const float* __restrict__ ab, const float* __restrict__ betab,
            const float* __restrict__ asp, const float* __restrict__ bsp,
            float* __restrict__ yout) {
    int bh = blockIdx.x;
    int b = bh / H_, h = bh % H_;
    int tid = threadIdx.x;
    int j = tid & 63, g = tid >> 6;

    __shared__ float sk[64], sq[64], sv[64], salpha[64], sspb[64];
    __shared__ float sred1[4][64], sred2[4][64];
    __shared__ float sbeta;

    float s[16];
    #pragma unroll
    for (int ii = 0; ii < 16; ii++) s[ii] = 0.f;

    float m = 0.f, aspv = 0.f, bspv = 0.f;
    if (tid < 64) { aspv = asp[h * 64 + tid]; bspv = bsp[h * 64 + tid]; }

    size_t rowbase = (size_t)(b * T_) * HD + (size_t)h * 64;
    const float* bb = betab + (size_t)(b * T_) * H_ + h;

    for (int t = 0; t < T_; t++) {
        size_t qo = rowbase + (size_t)t * HD;
        float myspike = 0.f;
        if (tid < 64) {
            int i = tid;
            m = 0.9f * m + drive[qo + i];
            float spk = (m > 0.5f) ? 1.f : 0.f;
            m -= spk * 0.5f;
            myspike = spk;
            float araw = ab[qo + i] + aspv * spk;
            salpha[i] = 1.f / (1.f + __expf(-araw));
            sspb[i] = spk * bspv;
            sk[i] = k[qo + i];
            sq[i] = q[qo + i];
        } else if (tid < 128) {
            sv[tid - 64] = v[qo + (tid - 64)];
        }
        int nspk = __syncthreads_count((tid < 64) && (myspike > 0.5f));
        bool active = nspk > 0;
        if (tid < 32) {
            float sbv = sspb[tid] + sspb[tid + 32];
            #pragma unroll
            for (int o = 16; o; o >>= 1) sbv += __shfl_down_sync(0xffffffffu, sbv, o);
            if (tid == 0) sbeta = sbv;
        }
        float predp = 0.f;
        #pragma unroll
        for (int ii = 0; ii < 16; ii++) {
            int i = (g << 4) + ii;
            float a = active ? salpha[i] : 1.f;
            float sval = s[ii] * a;
            s[ii] = sval;
            predp = fmaf(sk[i], sval, predp);
        }
        sred1[g][j] = predp;
        __syncthreads();
        float pred = sred1[0][j] + sred1[1][j] + sred1[2][j] + sred1[3][j];
        float beta = 0.f;
        if (active) {
            float braw = bb[(size_t)t * H_] + sbeta;
            beta = 1.f / (1.f + __expf(-braw));
        }
        float bd = beta * (sv[j] - pred);
        float outp = 0.f;
        #pragma unroll
        for (int ii = 0; ii < 16; ii++) {
            int i = (g << 4) + ii;
            float sval = fmaf(sk[i], bd, s[ii]);
            s[ii] = sval;
            outp = fmaf(sq[i], sval, outp);
        }
        sred2[g][j] = outp;
        __syncthreads();
        if (g == 0) yout[qo + j] = sred2[0][j] + sred2[1][j] + sred2[2][j] + sred2[3][j];
    }
}

// ---------------- host launch ----------------

template <typename Tsym>
static float* symaddr(const Tsym& s) {
    void* p = nullptr;
    cudaGetSymbolAddress(&p, s);
    return (float*)p;
}

static void gemm(const float* A, const float* Bm, const float* bias,
                 const float* resid, const float* gate, float* C,
                 int M, int N, int K, int mode) {
    dim3 grid((N + 63) / 64, M / 64);
    sgemm_kernel<<<grid, 256>>>(A, Bm, bias, resid, gate, C, M, N, K, mode);
}

static void tgemm(const float* A, const float* Bm, const float* resid,
                  const float* gate, float* C, int M, int N, int K, int mode) {
    dim3 grid(N / 128, M / 128);
    tf32_gemm_kernel<<<grid, 256>>>(A, Bm, resid, gate, C, M, N, K, mode);
}

extern "C" void kernel_launch(void* const* d_in, const int* in_sizes, int n_in,
                              void* d_out, int out_size) {
    const float* x          = (const float*)d_in[0];
    const float* norm_in_w  = (const float*)d_in[1];
    const float* conv_w     = (const float*)d_in[2];
    const float* conv_b     = (const float*)d_in[3];
    const float* Wq         = (const float*)d_in[4];
    const float* Wk         = (const float*)d_in[5];
    const float* Wv         = (const float*)d_in[6];
    const float* Wo         = (const float*)d_in[7];
    const float* Wspike     = (const float*)d_in[8];
    const float* Wau        = (const float*)d_in[9];
    const float* bau        = (const float*)d_in[10];
    const float* Wad        = (const float*)d_in[11];
    const float* bad        = (const float*)d_in[12];
    const float* alpha_sp   = (const float*)d_in[13];
    const float* Wbeta      = (const float*)d_in[14];
    const float* bbeta      = (const float*)d_in[15];
    const float* beta_sp    = (const float*)d_in[16];
    const float* head_nw    = (const float*)d_in[17];
    const float* Wu1        = (const float*)d_in[18];
    const float* bu1        = (const float*)d_in[19];
    const float* Wu2        = (const float*)d_in[20];
    const float* bu2        = (const float*)d_in[21];
    const float* ff_norm_w  = (const float*)d_in[22];
    const float* Wff1       = (const float*)d_in[23];
    const float* Wff3       = (const float*)d_in[24];
    const float* Wff2       = (const float*)d_in[25];
    float* out = (float*)d_out;

    float* p_tmp   = symaddr(g_tmp);
    float* p_h     = symaddr(g_h);
    float* p_q     = symaddr(g_q);
    float* p_k     = symaddr(g_k);
    float* p_v     = symaddr(g_v);
    float* p_drive = symaddr(g_drive);
    float* p_ab    = symaddr(g_ab);
    float* p_au    = symaddr(g_au);
    float* p_beta  = symaddr(g_beta);
    float* p_yattn = symaddr(g_yattn);
    float* p_u1    = symaddr(g_u1);
    float* p_gate  = symaddr(g_gate);
    float* p_y2    = symaddr(g_y2);
    float* p_z     = symaddr(g_z);
    float* p_ffa   = symaddr(g_ffa);

    // 1) input RMS norm
    rmsnorm_kernel<<<BT, 256>>>(x, norm_in_w, p_tmp);
    // 2) causal depthwise conv + silu
    conv_silu_kernel<<<(BT * D_ + 255) / 256, 256>>>(p_tmp, conv_w, conv_b, p_h);
    // 3) projections: q/k/v via tf32 tensor core; drive stays fp32 (spike-threshold sensitivity)
    tgemm(p_h, Wq, nullptr, nullptr, p_q, BT, HD, D_, EP_NONE);
    tgemm(p_h, Wk, nullptr, nullptr, p_k, BT, HD, D_, EP_NONE);
    tgemm(p_h, Wv, nullptr, nullptr, p_v, BT, HD, D_, EP_NONE);
    gemm(p_h, Wspike, nullptr, nullptr, nullptr, p_drive, BT, HD, D_, EP_NONE);
    // 4) alpha path (fp32, small)
    gemm(p_h, Wau, bau, nullptr, nullptr, p_au, BT, R_, D_, EP_BIAS_SILU);
    gemm(p_au, Wad, bad, nullptr, nullptr, p_ab, BT, HD, R_, EP_BIAS);
    // 5) beta base (fp32, tiny)
    gemm(p_h, Wbeta, bbeta, nullptr, nullptr, p_beta, BT, H_, D_, EP_BIAS);
    // 6) q/k L2 normalize per head
    l2norm_kernel<<<BT * H_, 64>>>(p_q);
    l2norm_kernel<<<BT * H_, 64>>>(p_k);
    // 7) output gate (fp32, small)
    gemm(x, Wu1, bu1, nullptr, nullptr, p_u1, BT, R_, D_, EP_BIAS_SILU);
    gemm(p_u1, Wu2, bu2, nullptr, nullptr, p_gate, BT, D_, R_, EP_BIAS_SIGMOID);
    // 8) sequential LIF + delta-rule scan
    scan_kernel<<<B_ * H_, 256>>>(p_q, p_k, p_v, p_drive, p_ab, p_beta,
                                  alpha_sp, beta_sp, p_yattn);
    // 9) headwise RMS norm
    headnorm_kernel<<<BT * H_, 64>>>(p_yattn, head_nw);
    // 10) y2 = x + (yattn@Wo) * gate  (tf32)
    tgemm(p_yattn, Wo, x, p_gate, p_y2, BT, D_, HD, EP_RESID_GATE);
    // 11) FFN: z = rms(y2); ffa = silu(z@Wff1)*(z@Wff3); out = y2 + ffa@Wff2
    rmsnorm_kernel<<<BT, 256>>>(p_y2, ff_norm_w, p_z);
    {
        dim3 grid(DFF / 64, BT / 128);
        tf32_dual_kernel<<<grid, 256>>>(p_z, Wff1, Wff3, p_ffa, BT, DFF, D_);
    }
    tgemm(p_ffa, Wff2, p_y2, nullptr, out, BT, D_, DFF, EP_RESID_ADD);
}

// round 3
// speedup vs baseline: 1.8020x; 1.6407x over previous
#include <cuda_runtime.h>
#include <mma.h>
#include <math.h>
#include <stdint.h>

using namespace nvcuda;

#define B_   2
#define T_   2048
#define D_   1024
#define H_   8
#define DK   64
#define DV   64
#define R_   64
#define DFF  4096
#define BT   (B_*T_)       // 4096
#define HD   (H_*DK)       // 512

// ---------------- scratch (device globals; no allocation allowed) ----------------
__device__ float g_tmp  [BT*D_];
__device__ float g_h    [BT*D_];
__device__ float g_q    [BT*HD];
__device__ float g_k    [BT*HD];
__device__ float g_v    [BT*HD];
__device__ float g_drive[BT*HD];
__device__ float g_ab   [BT*HD];
__device__ float g_au   [BT*R_];
__device__ float g_beta [BT*H_];
__device__ float g_yattn[BT*HD];
__device__ float g_u1   [BT*R_];
__device__ float g_gate [BT*D_];
__device__ float g_y2   [BT*D_];
__device__ float g_z    [BT*D_];
__device__ float g_ffa  [BT*DFF];

// ---------------- cp.async helpers ----------------
__device__ __forceinline__ void cp_async16(uint32_t dst, const void* src) {
    asm volatile("cp.async.cg.shared.global [%0], [%1], 16;\n" :: "r"(dst), "l"(src));
}
__device__ __forceinline__ void cp_commit() { asm volatile("cp.async.commit_group;\n" ::: "memory"); }
__device__ __forceinline__ void cp_wait1() { asm volatile("cp.async.wait_group 1;\n" ::: "memory"); }
__device__ __forceinline__ void cp_wait0() { asm volatile("cp.async.wait_group 0;\n" ::: "memory"); }

// ---------------- packed f32x2 helpers (Blackwell FFMA2 pipe) ----------------
struct f32x2 { unsigned long long v; };
__device__ __forceinline__ f32x2 f2_zero() { f32x2 r; r.v = 0ull; return r; }
__device__ __forceinline__ f32x2 f2_bcast(float x) {
    f32x2 r; asm("mov.b64 %0, {%1, %1};" : "=l"(r.v) : "f"(x)); return r;
}
__device__ __forceinline__ f32x2 f2_mul(f32x2 a, f32x2 b) {
    f32x2 r; asm("mul.rn.f32x2 %0, %1, %2;" : "=l"(r.v) : "l"(a.v), "l"(b.v)); return r;
}
__device__ __forceinline__ f32x2 f2_fma(f32x2 a, f32x2 b, f32x2 c) {
    f32x2 r; asm("fma.rn.f32x2 %0, %1, %2, %3;" : "=l"(r.v) : "l"(a.v), "l"(b.v), "l"(c.v)); return r;
}
__device__ __forceinline__ float f2_hadd(f32x2 a) {
    float x, y; asm("mov.b64 {%0, %1}, %2;" : "=f"(x), "=f"(y) : "l"(a.v)); return x + y;
}

// ---------------- elementwise / norm kernels ----------------

__global__ void rmsnorm_kernel(const float* __restrict__ x, const float* __restrict__ w,
                               float* __restrict__ out) {
    int row = blockIdx.x;
    const float* xr = x + (size_t)row * D_;
    float ss = 0.f;
    for (int i = threadIdx.x; i < D_; i += 256) { float v = xr[i]; ss += v * v; }
    #pragma unroll
    for (int o = 16; o; o >>= 1) ss += __shfl_down_sync(0xffffffffu, ss, o);
    __shared__ float sh[8];
    int lane = threadIdx.x & 31, warp = threadIdx.x >> 5;
    if (lane == 0) sh[warp] = ss;
    __syncthreads();
    if (warp == 0) {
        ss = (lane < 8) ? sh[lane] : 0.f;
        #pragma unroll
        for (int o = 4; o; o >>= 1) ss += __shfl_down_sync(0xffffffffu, ss, o);
        if (lane == 0) sh[0] = ss;
    }
    __syncthreads();
    float inv = rsqrtf(sh[0] * (1.f / D_) + 1e-6f);
    for (int i = threadIdx.x; i < D_; i += 256)
        out[(size_t)row * D_ + i] = xr[i] * inv * w[i];
}

__global__ void conv_silu_kernel(const float* __restrict__ hin, const float* __restrict__ w,
                                 const float* __restrict__ b, float* __restrict__ out) {
    int idx = blockIdx.x * blockDim.x + threadIdx.x;
    if (idx >= BT * D_) return;
    int d = idx % D_;
    int bt = idx / D_;
    int t = bt % T_;
    float acc = b[d];
    #pragma unroll
    for (int j = 0; j < 4; j++) {
        int tt = t - 3 + j;
        if (tt >= 0) acc += hin[(size_t)(bt - 3 + j) * D_ + d] * w[d * 4 + j];
    }
    out[idx] = acc / (1.f + __expf(-acc));
}

// fused q+k L2 normalize (blockIdx.y selects tensor)
__global__ void l2norm2_kernel(float* __restrict__ pq, float* __restrict__ pk) {
    float* p = blockIdx.y ? pk : pq;
    size_t base = (size_t)blockIdx.x * 64;
    float v = p[base + threadIdx.x];
    float ss = v * v;
    #pragma unroll
    for (int o = 16; o; o >>= 1) ss += __shfl_down_sync(0xffffffffu, ss, o);
    __shared__ float sh[2];
    if ((threadIdx.x & 31) == 0) sh[threadIdx.x >> 5] = ss;
    __syncthreads();
    float tot = sh[0] + sh[1];
    p[base + threadIdx.x] = v / (sqrtf(tot) + 1e-6f);
}

__global__ void headnorm_kernel(float* __restrict__ p, const float* __restrict__ w) {
    int h = blockIdx.x % H_;
    size_t base = (size_t)blockIdx.x * 64;
    float v = p[base + threadIdx.x];
    float ss = v * v;
    #pragma unroll
    for (int o = 16; o; o >>= 1) ss += __shfl_down_sync(0xffffffffu, ss, o);
    __shared__ float sh[2];
    if ((threadIdx.x & 31) == 0) sh[threadIdx.x >> 5] = ss;
    __syncthreads();
    float mean = (sh[0] + sh[1]) * (1.f / 64.f);
    p[base + threadIdx.x] = v * rsqrtf(mean + 1e-6f) * w[h * 64 + threadIdx.x];
}

// ---------------- fp32 SIMT GEMM (spike path + small GEMMs) ----------------

enum { EP_NONE = 0, EP_BIAS = 1, EP_BIAS_SILU = 2, EP_BIAS_SIGMOID = 3,
       EP_RESID_GATE = 4, EP_RESID_ADD = 5 };

__global__ void __launch_bounds__(256)
sgemm_kernel(const float* __restrict__ A, const float* __restrict__ Bm,
             const float* __restrict__ bias, const float* __restrict__ resid,
             const float* __restrict__ gate, float* __restrict__ C,
             int M, int N, int K, int mode) {
    __shared__ float As[16][68];
    __shared__ float Bs[16][64];
    int tid = threadIdx.x;
    int tx = tid & 15, ty = tid >> 4;
    int row0 = blockIdx.y * 64;
    int col0 = blockIdx.x * 64;

    int aRow = tid >> 2, aCol = (tid & 3) * 4;
    int bRow = tid >> 4, bCol = (tid & 15) * 4;
    const bool fullN = (col0 + 64 <= N);

    float acc[4][4];
    #pragma unroll
    for (int i = 0; i < 4; i++)
        #pragma unroll
        for (int j = 0; j < 4; j++) acc[i][j] = 0.f;

    for (int k0 = 0; k0 < K; k0 += 16) {
        float4 av = *reinterpret_cast<const float4*>(&A[(size_t)(row0 + aRow) * K + k0 + aCol]);
        As[aCol + 0][aRow] = av.x; As[aCol + 1][aRow] = av.y;
        As[aCol + 2][aRow] = av.z; As[aCol + 3][aRow] = av.w;
        if (fullN) {
            *reinterpret_cast<float4*>(&Bs[bRow][bCol]) =
                *reinterpret_cast<const float4*>(&Bm[(size_t)(k0 + bRow) * N + col0 + bCol]);
        } else {
            #pragma unroll
            for (int u = 0; u < 4; u++) {
                int c = col0 + bCol + u;
                Bs[bRow][bCol + u] = (c < N) ? Bm[(size_t)(k0 + bRow) * N + c] : 0.f;
            }
        }
        __syncthreads();
        #pragma unroll
        for (int kk = 0; kk < 16; kk++) {
            float a[4], b[4];
            *reinterpret_cast<float4*>(a) = *reinterpret_cast<const float4*>(&As[kk][ty * 4]);
            *reinterpret_cast<float4*>(b) = *reinterpret_cast<const float4*>(&Bs[kk][tx * 4]);
            #pragma unroll
            for (int i = 0; i < 4; i++)
                #pragma unroll
                for (int j = 0; j < 4; j++) acc[i][j] = fmaf(a[i], b[j], acc[i][j]);
        }
        __syncthreads();
    }

    #pragma unroll
    for (int i = 0; i < 4; i++) {
        int r = row0 + ty * 4 + i;
        #pragma unroll
        for (int j = 0; j < 4; j++) {
            int c = col0 + tx * 4 + j;
            if (c >= N) continue;
            float a = acc[i][j], o;
            if (mode == EP_NONE) o = a;
            else if (mode == EP_BIAS) o = a + bias[c];
            else if (mode == EP_BIAS_SILU) { float t = a + bias[c]; o = t / (1.f + __expf(-t)); }
            else if (mode == EP_BIAS_SIGMOID) { float t = a + bias[c]; o = 1.f / (1.f + __expf(-t)); }
            else if (mode == EP_RESID_GATE) o = resid[(size_t)r * N + c] + a * gate[(size_t)r * N + c];
            else o = resid[(size_t)r * N + c] + a;
            C[(size_t)r * N + c] = o;
        }
    }
}

// ---------------- tf32 GEMM v2: cp.async double-buffered, padded smem ----------------
// C[M,N] = A[M,K] @ B[K,N]; M%128==0, N%128==0, K%16==0.
// Block 256 thr (8 warps 4x2), block tile 128x128, warp tile 32x64, K-stage 16.

#define LDA2 20
#define LDB2 132

__device__ __forceinline__ void tf32_core_epilogue(
    wmma::fragment<wmma::accumulator, 16, 16, 8, float> (&acc)[2][4],
    const float* resid, const float* gate, float* C,
    int row0, int col0, int N, int warpM, int warpN, int mode)
{
    #pragma unroll
    for (int i = 0; i < 2; i++) {
        #pragma unroll
        for (int j = 0; j < 4; j++) {
            int r = row0 + warpM * 32 + i * 16;
            int c = col0 + warpN * 64 + j * 16;
            if (mode == EP_RESID_ADD) {
                wmma::fragment<wmma::accumulator, 16, 16, 8, float> rf;
                wmma::load_matrix_sync(rf, &resid[(size_t)r * N + c], N, wmma::mem_row_major);
                #pragma unroll
                for (int e = 0; e < rf.num_elements; e++) acc[i][j].x[e] += rf.x[e];
            } else if (mode == EP_RESID_GATE) {
                wmma::fragment<wmma::accumulator, 16, 16, 8, float> rf, gf;
                wmma::load_matrix_sync(rf, &resid[(size_t)r * N + c], N, wmma::mem_row_major);
                wmma::load_matrix_sync(gf, &gate[(size_t)r * N + c], N, wmma::mem_row_major);
                #pragma unroll
                for (int e = 0; e < rf.num_elements; e++)
                    acc[i][j].x[e] = rf.x[e] + acc[i][j].x[e] * gf.x[e];
            }
            wmma::store_matrix_sync(&C[(size_t)r * N + c], acc[i][j], N, wmma::mem_row_major);
        }
    }
}

__device__ __forceinline__ void tf32_core(
    const float* __restrict__ A, const float* __restrict__ Bm,
    const float* __restrict__ resid, const float* __restrict__ gate,
    float* __restrict__ C, int N, int K, int mode,
    int row0, int col0, float* sA, float* sB)
{
    int tid = threadIdx.x;
    int warp = tid >> 5, warpM = warp & 3, warpN = warp >> 2;

    uint32_t sAu = (uint32_t)__cvta_generic_to_shared(sA);
    uint32_t sBu = (uint32_t)__cvta_generic_to_shared(sB);

    int ar = tid >> 2, ac = (tid & 3) << 2;      // A: 2 float4/thread (rows ar, ar+64)
    int br = tid >> 5, bc = (tid & 31) << 2;     // B: 2 float4/thread (rows br, br+8)

    wmma::fragment<wmma::accumulator, 16, 16, 8, float> acc[2][4];
    #pragma unroll
    for (int i = 0; i < 2; i++)
        #pragma unroll
        for (int j = 0; j < 4; j++) wmma::fill_fragment(acc[i][j], 0.f);

    int nk = K >> 4;
    // issue stage 0
    {
        cp_async16(sAu + (uint32_t)((ar) * LDA2 + ac) * 4u, &A[(size_t)(row0 + ar) * K + ac]);
        cp_async16(sAu + (uint32_t)((ar + 64) * LDA2 + ac) * 4u, &A[(size_t)(row0 + ar + 64) * K + ac]);
        cp_async16(sBu + (uint32_t)((br) * LDB2 + bc) * 4u, &Bm[(size_t)(br) * N + col0 + bc]);
        cp_async16(sBu + (uint32_t)((br + 8) * LDB2 + bc) * 4u, &Bm[(size_t)(br + 8) * N + col0 + bc]);
        cp_commit();
    }
    for (int ks = 0; ks < nk; ks++) {
        int buf = ks & 1;
        if (ks + 1 < nk) {
            int k0 = (ks + 1) << 4;
            uint32_t oA = (uint32_t)(((buf ^ 1) * 128 * LDA2) * 4);
            uint32_t oB = (uint32_t)(((buf ^ 1) * 16 * LDB2) * 4);
            cp_async16(sAu + oA + (uint32_t)((ar) * LDA2 + ac) * 4u, &A[(size_t)(row0 + ar) * K + k0 + ac]);
            cp_async16(sAu + oA + (uint32_t)((ar + 64) * LDA2 + ac) * 4u, &A[(size_t)(row0 + ar + 64) * K + k0 + ac]);
            cp_async16(sBu + oB + (uint32_t)((br) * LDB2 + bc) * 4u, &Bm[(size_t)(k0 + br) * N + col0 + bc]);
            cp_async16(sBu + oB + (uint32_t)((br + 8) * LDB2 + bc) * 4u, &Bm[(size_t)(k0 + br + 8) * N + col0 + bc]);
            cp_commit();
            cp_wait1();
        } else {
            cp_wait0();
        }
        __syncthreads();
        float* cA = sA + buf * 128 * LDA2;
        float* cB = sB + buf * 16 * LDB2;
        #pragma unroll
        for (int kk = 0; kk < 16; kk += 8) {
            wmma::fragment<wmma::matrix_a, 16, 16, 8, wmma::precision::tf32, wmma::row_major> af[2];
            wmma::fragment<wmma::matrix_b, 16, 16, 8, wmma::precision::tf32, wmma::row_major> bf[4];
            #pragma unroll
            for (int i = 0; i < 2; i++) {
                wmma::load_matrix_sync(af[i], &cA[(warpM * 32 + i * 16) * LDA2 + kk], LDA2);
                #pragma unroll
                for (int e = 0; e < af[i].num_elements; e++)
                    af[i].x[e] = wmma::__float_to_tf32(af[i].x[e]);
            }
            #pragma unroll
            for (int j = 0; j < 4; j++) {
                wmma::load_matrix_sync(bf[j], &cB[kk * LDB2 + warpN * 64 + j * 16], LDB2);
                #pragma unroll
                for (int e = 0; e < bf[j].num_elements; e++)
                    bf[j].x[e] = wmma::__float_to_tf32(bf[j].x[e]);
            }
            #pragma unroll
            for (int i = 0; i < 2; i++)
                #pragma unroll
                for (int j = 0; j < 4; j++)
                    wmma::mma_sync(acc[i][j], af[i], bf[j], acc[i][j]);
        }
        __syncthreads();
    }
    tf32_core_epilogue(acc, resid, gate, C, row0, col0, N, warpM, warpN, mode);
}

__global__ void __launch_bounds__(256)
tf32_gemm2_kernel(const float* __restrict__ A, const float* __restrict__ Bm,
                  const float* __restrict__ resid, const float* __restrict__ gate,
                  float* __restrict__ C, int N, int K, int mode) {
    __shared__ float sA[2 * 128 * LDA2];
    __shared__ float sB[2 * 16 * LDB2];
    tf32_core(A, Bm, resid, gate, C, N, K, mode,
              blockIdx.y * 128, blockIdx.x * 128, sA, sB);
}

// fused QKV: blockIdx.z selects weight/output
__global__ void __launch_bounds__(256)
tf32_qkv_kernel(const float* __restrict__ A,
                const float* __restrict__ Wq, const float* __restrict__ Wk,
                const float* __restrict__ Wv,
                float* __restrict__ Cq, float* __restrict__ Ck, float* __restrict__ Cv,
                int N, int K) {
    __shared__ float sA[2 * 128 * LDA2];
    __shared__ float sB[2 * 16 * LDB2];
    const float* Bm = (blockIdx.z == 0) ? Wq : (blockIdx.z == 1) ? Wk : Wv;
    float* C = (blockIdx.z == 0) ? Cq : (blockIdx.z == 1) ? Ck : Cv;
    tf32_core(A, Bm, nullptr, nullptr, C, N, K, EP_NONE,
              blockIdx.y * 128, blockIdx.x * 128, sA, sB);
}

// tf32 dual GEMM v2: C = silu(A@B1) * (A@B3). Tile 128x64, warp 32x32.
#define LDBD 68
__global__ void __launch_bounds__(256)
tf32_dual2_kernel(const float* __restrict__ A, const float* __restrict__ B1,
                  const float* __restrict__ B3, float* __restrict__ C,
                  int N, int K) {
    __shared__ float sA[2 * 128 * LDA2];
    __shared__ float sB1[2 * 16 * LDBD];
    __shared__ float sB3[2 * 16 * LDBD];
    int tid = threadIdx.x;
    int warp = tid >> 5, warpM = warp & 3, warpN = warp >> 2;
    int row0 = blockIdx.y * 128;
    int col0 = blockIdx.x * 64;

    uint32_t sAu = (uint32_t)__cvta_generic_to_shared(sA);
    uint32_t sB1u = (uint32_t)__cvta_generic_to_shared(sB1);
    uint32_t sB3u = (uint32_t)__cvta_generic_to_shared(sB3);

    int ar = tid >> 2, ac = (tid & 3) << 2;
    int br = tid >> 4, bc = (tid & 15) << 2;   // 16x64 = 256 float4: 1 per thread per matrix

    wmma::fragment<wmma::accumulator, 16, 16, 8, float> acc1[2][2], acc3[2][2];
    #pragma unroll
    for (int i = 0; i < 2; i++)
        #pragma unroll
        for (int j = 0; j < 2; j++) { wmma::fill_fragment(acc1[i][j], 0.f); wmma::fill_fragment(acc3[i][j], 0.f); }

    int nk = K >> 4;
    {
        cp_async16(sAu + (uint32_t)((ar) * LDA2 + ac) * 4u, &A[(size_t)(row0 + ar) * K + ac]);
        cp_async16(sAu + (uint32_t)((ar + 64) * LDA2 + ac) * 4u, &A[(size_t)(row0 + ar + 64) * K + ac]);
        cp_async16(sB1u + (uint32_t)(br * LDBD + bc) * 4u, &B1[(size_t)br * N + col0 + bc]);
        cp_async16(sB3u + (uint32_t)(br * LDBD + bc) * 4u, &B3[(size_t)br * N + col0 + bc]);
        cp_commit();
    }
    for (int ks = 0; ks < nk; ks++) {
        int buf = ks & 1;
        if (ks + 1 < nk) {
            int k0 = (ks + 1) << 4;
            uint32_t oA = (uint32_t)(((buf ^ 1) * 128 * LDA2) * 4);
            uint32_t oB = (uint32_t)(((buf ^ 1) * 16 * LDBD) * 4);
            cp_async16(sAu + oA + (uint32_t)((ar) * LDA2 + ac) * 4u, &A[(size_t)(row0 + ar) * K + k0 + ac]);
            cp_async16(sAu + oA + (uint32_t)((ar + 64) * LDA2 + ac) * 4u, &A[(size_t)(row0 + ar + 64) * K + k0 + ac]);
            cp_async16(sB1u + oB + (uint32_t)(br * LDBD + bc) * 4u, &B1[(size_t)(k0 + br) * N + col0 + bc]);
            cp_async16(sB3u + oB + (uint32_t)(br * LDBD + bc) * 4u, &B3[(size_t)(k0 + br) * N + col0 + bc]);
            cp_commit();
            cp_wait1();
        } else {
            cp_wait0();
        }
        __syncthreads();
        float* cA = sA + buf * 128 * LDA2;
        float* cB1 = sB1 + buf * 16 * LDBD;
        float* cB3 = sB3 + buf * 16 * LDBD;
        #pragma unroll
        for (int kk = 0; kk < 16; kk += 8) {
            wmma::fragment<wmma::matrix_a, 16, 16, 8, wmma::precision::tf32, wmma::row_major> af[2];
            wmma::fragment<wmma::matrix_b, 16, 16, 8, wmma::precision::tf32, wmma::row_major> b1f[2], b3f[2];
            #pragma unroll
            for (int i = 0; i < 2; i++) {
                wmma::load_matrix_sync(af[i], &cA[(warpM * 32 + i * 16) * LDA2 + kk], LDA2);
                #pragma unroll
                for (int e = 0; e < af[i].num_elements; e++)
                    af[i].x[e] = wmma::__float_to_tf32(af[i].x[e]);
            }
            #pragma unroll
            for (int j = 0; j < 2; j++) {
                wmma::load_matrix_sync(b1f[j], &cB1[kk * LDBD + warpN * 32 + j * 16], LDBD);
                wmma::load_matrix_sync(b3f[j], &cB3[kk * LDBD + warpN * 32 + j * 16], LDBD);
                #pragma unroll
                for (int e = 0; e < b1f[j].num_elements; e++) {
                    b1f[j].x[e] = wmma::__float_to_tf32(b1f[j].x[e]);
                    b3f[j].x[e] = wmma::__float_to_tf32(b3f[j].x[e]);
                }
            }
            #pragma unroll
            for (int i = 0; i < 2; i++)
                #pragma unroll
                for (int j = 0; j < 2; j++) {
                    wmma::mma_sync(acc1[i][j], af[i], b1f[j], acc1[i][j]);
                    wmma::mma_sync(acc3[i][j], af[i], b3f[j], acc3[i][j]);
                }
        }
        __syncthreads();
    }
    #pragma unroll
    for (int i = 0; i < 2; i++)
        #pragma unroll
        for (int j = 0; j < 2; j++) {
            #pragma unroll
            for (int e = 0; e < acc1[i][j].num_elements; e++) {
                float t = acc1[i][j].x[e];
                acc1[i][j].x[e] = (t / (1.f + __expf(-t))) * acc3[i][j].x[e];
            }
            int r = row0 + warpM * 32 + i * 16;
            int c = col0 + warpN * 32 + j * 16;
            wmma::store_matrix_sync(&C[(size_t)r * N + c], acc1[i][j], N, wmma::mem_row_major);
        }
}

// ---------------- scan v2: column-per-thread, packed f32x2, 1 barrier/step ----------------
// 64 threads per (b,h) block; thread j owns S[:,j] (64 floats = 32 f32x2 regs).
__global__ void __launch_bounds__(64)
scan2_kernel(const float* __restrict__ q, const float* __restrict__ k,
             const float* __restrict__ v, const float* __restrict__ drive,
             const float* __restrict__ ab, const float* __restrict__ betab,
             const float* __restrict__ asp, const float* __restrict__ bsp,
             float* __restrict__ yout) {
    int bh = blockIdx.x;
    int b = bh / H_, h = bh % H_;
    int tid = threadIdx.x;           // 0..63 = both LIF lane i and v-column j
    int lane = tid & 31, warp = tid >> 5;

    __shared__ __align__(8) float sk[2][64], sq_[2][64], sal[2][64];
    __shared__ float wsum[2][2];

    f32x2 s2[32];
    #pragma unroll
    for (int i = 0; i < 32; i++) s2[i] = f2_zero();

    float m = 0.f;
    float aspv = asp[h * 64 + tid];
    float bspv = bsp[h * 64 + tid];

    size_t rowbase = (size_t)(b * T_) * HD + (size_t)h * 64;
    const float* bb = betab + (size_t)(b * T_) * H_ + h;

    size_t qo = rowbase;
    float dv_ = drive[qo + tid], abv = ab[qo + tid];
    float kv = k[qo + tid], qv = q[qo + tid], vv = v[qo + tid];
    float bbv = bb[0];

    for (int t = 0; t < T_; t++) {
        int pb = t & 1;
        size_t qn = qo + HD;
        // LIF for lane i = tid
        m = 0.9f * m + dv_;
        float spk = (m > 0.5f) ? 1.f : 0.f;
        m -= 0.5f * spk;
        float al = 1.f / (1.f + __expf(-(abv + aspv * spk)));
        sk[pb][tid] = kv;
        sq_[pb][tid] = qv;
        sal[pb][tid] = al;
        float sb = spk * bspv;
        #pragma unroll
        for (int o = 16; o; o >>= 1) sb += __shfl_down_sync(0xffffffffu, sb, o);
        if (lane == 0) wsum[pb][warp] = sb;
        float vcur = vv, bbcur = bbv;
        // prefetch next step's operands (overlaps with barrier+compute)
        if (t + 1 < T_) {
            dv_ = drive[qn + tid]; abv = ab[qn + tid];
            kv = k[qn + tid]; qv = q[qn + tid]; vv = v[qn + tid];
            bbv = bb[(size_t)(t + 1) * H_];
        }
        int cnt = __syncthreads_count(spk > 0.5f);
        const unsigned long long* k2 = (const unsigned long long*)sk[pb];
        const unsigned long long* q2 = (const unsigned long long*)sq_[pb];
        const unsigned long long* a2 = (const unsigned long long*)sal[pb];
        float out;
        if (cnt > 0) {
            f32x2 pred2 = f2_zero();
            f32x2 kr[32];
            #pragma unroll
            for (int i = 0; i < 32; i++) {
                kr[i].v = k2[i];
                f32x2 av; av.v = a2[i];
                s2[i] = f2_mul(s2[i], av);
                pred2 = f2_fma(kr[i], s2[i], pred2);
            }
            float pred = f2_hadd(pred2);
            float braw = bbcur + wsum[pb][0] + wsum[pb][1];
            float beta = 1.f / (1.f + __expf(-braw));
            float bd = beta * (vcur - pred);
            f32x2 bd2 = f2_bcast(bd);
            f32x2 out2 = f2_zero();
            #pragma unroll
            for (int i = 0; i < 32; i++) {
                f32x2 qr; qr.v = q2[i];
                s2[i] = f2_fma(kr[i], bd2, s2[i]);
                out2 = f2_fma(qr, s2[i], out2);
            }
            out = f2_hadd(out2);
        } else {
            // inactive: alpha=1, beta=0 -> state unchanged; out = q . S
            f32x2 out2 = f2_zero();
            #pragma unroll
            for (int i = 0; i < 32; i++) {
                f32x2 qr; qr.v = q2[i];
                out2 = f2_fma(qr, s2[i], out2);
            }
            out = f2_hadd(out2);
        }
        yout[qo + tid] = out;
        qo = qn;
    }
}

// ---------------- host launch ----------------

template <typename Tsym>
static float* symaddr(const Tsym& s) {
    void* p = nullptr;
    cudaGetSymbolAddress(&p, s);
    return (float*)p;
}

static void gemm(const float* A, const float* Bm, const float* bias,
                 const float* resid, const float* gate, float* C,
                 int M, int N, int K, int mode) {
    dim3 grid((N + 63) / 64, M / 64);
    sgemm_kernel<<<grid, 256>>>(A, Bm, bias, resid, gate, C, M, N, K, mode);
}

static void tgemm2(const float* A, const float* Bm, const float* resid,
                   const float* gate, float* C, int M, int N, int K, int mode) {
    dim3 grid(N / 128, M / 128);
    tf32_gemm2_kernel<<<grid, 256>>>(A, Bm, resid, gate, C, N, K, mode);
}

extern "C" void kernel_launch(void* const* d_in, const int* in_sizes, int n_in,
                              void* d_out, int out_size) {
    const float* x          = (const float*)d_in[0];
    const float* norm_in_w  = (const float*)d_in[1];
    const float* conv_w     = (const float*)d_in[2];
    const float* conv_b     = (const float*)d_in[3];
    const float* Wq         = (const float*)d_in[4];
    const float* Wk         = (const float*)d_in[5];
    const float* Wv         = (const float*)d_in[6];
    const float* Wo         = (const float*)d_in[7];
    const float* Wspike     = (const float*)d_in[8];
    const float* Wau        = (const float*)d_in[9];
    const float* bau        = (const float*)d_in[10];
    const float* Wad        = (const float*)d_in[11];
    const float* bad        = (const float*)d_in[12];
    const float* alpha_sp   = (const float*)d_in[13];
    const float* Wbeta      = (const float*)d_in[14];
    const float* bbeta      = (const float*)d_in[15];
    const float* beta_sp    = (const float*)d_in[16];
    const float* head_nw    = (const float*)d_in[17];
    const float* Wu1        = (const float*)d_in[18];
    const float* bu1        = (const float*)d_in[19];
    const float* Wu2        = (const float*)d_in[20];
    const float* bu2        = (const float*)d_in[21];
    const float* ff_norm_w  = (const float*)d_in[22];
    const float* Wff1       = (const float*)d_in[23];
    const float* Wff3       = (const float*)d_in[24];
    const float* Wff2       = (const float*)d_in[25];
    float* out = (float*)d_out;

    float* p_tmp   = symaddr(g_tmp);
    float* p_h     = symaddr(g_h);
    float* p_q     = symaddr(g_q);
    float* p_k     = symaddr(g_k);
    float* p_v     = symaddr(g_v);
    float* p_drive = symaddr(g_drive);
    float* p_ab    = symaddr(g_ab);
    float* p_au    = symaddr(g_au);
    float* p_beta  = symaddr(g_beta);
    float* p_yattn = symaddr(g_yattn);
    float* p_u1    = symaddr(g_u1);
    float* p_gate  = symaddr(g_gate);
    float* p_y2    = symaddr(g_y2);
    float* p_z     = symaddr(g_z);
    float* p_ffa   = symaddr(g_ffa);

    // 1) input RMS norm
    rmsnorm_kernel<<<BT, 256>>>(x, norm_in_w, p_tmp);
    // 2) causal depthwise conv + silu
    conv_silu_kernel<<<(BT * D_ + 255) / 256, 256>>>(p_tmp, conv_w, conv_b, p_h);
    // 3) fused q/k/v projections (tf32, full chip); drive stays fp32 (spike threshold)
    {
        dim3 grid(HD / 128, BT / 128, 3);
        tf32_qkv_kernel<<<grid, 256>>>(p_h, Wq, Wk, Wv, p_q, p_k, p_v, HD, D_);
    }
    gemm(p_h, Wspike, nullptr, nullptr, nullptr, p_drive, BT, HD, D_, EP_NONE);
    // 4) alpha path (fp32, small)
    gemm(p_h, Wau, bau, nullptr, nullptr, p_au, BT, R_, D_, EP_BIAS_SILU);
    gemm(p_au, Wad, bad, nullptr, nullptr, p_ab, BT, HD, R_, EP_BIAS);
    // 5) beta base (fp32, tiny)
    gemm(p_h, Wbeta, bbeta, nullptr, nullptr, p_beta, BT, H_, D_, EP_BIAS);
    // 6) q/k L2 normalize per head (fused launch)
    {
        dim3 grid(BT * H_, 2);
        l2norm2_kernel<<<grid, 64>>>(p_q, p_k);
    }
    // 7) output gate (fp32, small)
    gemm(x, Wu1, bu1, nullptr, nullptr, p_u1, BT, R_, D_, EP_BIAS_SILU);
    gemm(p_u1, Wu2, bu2, nullptr, nullptr, p_gate, BT, D_, R_, EP_BIAS_SIGMOID);
    // 8) sequential LIF + delta-rule scan (column-per-thread, f32x2)
    scan2_kernel<<<B_ * H_, 64>>>(p_q, p_k, p_v, p_drive, p_ab, p_beta,
                                  alpha_sp, beta_sp, p_yattn);
    // 9) headwise RMS norm
    headnorm_kernel<<<BT * H_, 64>>>(p_yattn, head_nw);
    // 10) y2 = x + (yattn@Wo) * gate  (tf32)
    tgemm2(p_yattn, Wo, x, p_gate, p_y2, BT, D_, HD, EP_RESID_GATE);
    // 11) FFN
    rmsnorm_kernel<<<BT, 256>>>(p_y2, ff_norm_w, p_z);
    {
        dim3 grid(DFF / 64, BT / 128);
        tf32_dual2_kernel<<<grid, 256>>>(p_z, Wff1, Wff3, p_ffa, DFF, D_);
    }
    tgemm2(p_ffa, Wff2, p_y2, nullptr, out, BT, D_, DFF, EP_RESID_ADD);
}